// round 3
// baseline (speedup 1.0000x reference)
#include <cuda_runtime.h>
#include <cstdint>

#define NN 50000
#define EE 1600000
#define DD 128
#define GG 64
#define IN_F 9

// ---------------- scratch: __device__ globals, referenced directly ----------
__device__ float    d_h0[NN * DD];
__device__ float    d_h1[NN * DD];
__device__ float    d_nmean[NN * DD];
__device__ int      d_deg[NN];
__device__ int      d_cursor[NN];
__device__ int      d_rowstart[NN + 1];
__device__ int      d_csr[EE];
__device__ float    d_gsum[GG * DD];
__device__ unsigned d_gmax[GG * DD];
__device__ int      d_gcnt[GG];

// buffer selectors (compile-time)
#define B_H0  0
#define B_H1  1
#define B_NM  2
#define B_EXT 3

template <int B>
__device__ __forceinline__ float* buf_ptr(float* ext) {
    if (B == B_H0) return d_h0;
    if (B == B_H1) return d_h1;
    if (B == B_NM) return d_nmean;
    return ext;
}
template <int B>
__device__ __forceinline__ const float* cbuf_ptr(const float* ext) {
    if (B == B_H0) return d_h0;
    if (B == B_H1) return d_h1;
    if (B == B_NM) return d_nmean;
    return ext;
}

// ---------------- init: zero counters/accumulators ---------------------------
__global__ void init_kernel() {
    int i = blockIdx.x * blockDim.x + threadIdx.x;
    if (i < NN) { d_deg[i] = 0; d_cursor[i] = 0; }
    if (i < GG) d_gcnt[i] = 0;
    if (i < GG * DD) { d_gsum[i] = 0.f; d_gmax[i] = 0u; }
}

// ---------------- degree count (edge_index is int32!) ------------------------
__global__ void count_deg_kernel(const int* __restrict__ ei) {
    int e = blockIdx.x * blockDim.x + threadIdx.x;
    if (e < EE) atomicAdd(&d_deg[ei[EE + e]], 1);
}

// ---------------- graph node counts ------------------------------------------
__global__ void gcnt_kernel(const int* __restrict__ batch) {
    int n = blockIdx.x * blockDim.x + threadIdx.x;
    if (n < NN) atomicAdd(&d_gcnt[batch[n]], 1);
}

// ---------------- exclusive scan of deg -> rowstart (single block) ----------
__global__ void scan_kernel() {
    __shared__ int sm[1024];
    __shared__ int srun;
    int t = threadIdx.x;
    if (t == 0) { srun = 0; d_rowstart[0] = 0; }
    __syncthreads();
    for (int base = 0; base < NN; base += 1024) {
        int i = base + t;
        int v = (i < NN) ? d_deg[i] : 0;
        sm[t] = v;
        __syncthreads();
        for (int off = 1; off < 1024; off <<= 1) {
            int tmp = (t >= off) ? sm[t - off] : 0;
            __syncthreads();
            sm[t] += tmp;
            __syncthreads();
        }
        int run = srun;
        if (i < NN) d_rowstart[i + 1] = run + sm[t];
        __syncthreads();
        if (t == 0) srun = run + sm[1023];
        __syncthreads();
    }
}

// ---------------- CSR fill ---------------------------------------------------
__global__ void fill_csr_kernel(const int* __restrict__ ei) {
    int e = blockIdx.x * blockDim.x + threadIdx.x;
    if (e < EE) {
        int src = ei[e];
        int dst = ei[EE + e];
        int pos = d_rowstart[dst] + atomicAdd(&d_cursor[dst], 1);
        d_csr[pos] = src;
    }
}

// ---------------- neighbor mean aggregation (1 warp per dst node) -----------
template <int SB>
__global__ void __launch_bounds__(256) aggregate_kernel() {
    const float* __restrict__ h = cbuf_ptr<SB>(nullptr);
    int warp = (blockIdx.x * blockDim.x + threadIdx.x) >> 5;
    int lane = threadIdx.x & 31;
    if (warp >= NN) return;
    int s = d_rowstart[warp];
    int e = d_rowstart[warp + 1];
    float4 acc = make_float4(0.f, 0.f, 0.f, 0.f);
    for (int i = s; i < e; i++) {
        int src = d_csr[i];
        float4 v = *(const float4*)(h + (size_t)src * DD + lane * 4);
        acc.x += v.x; acc.y += v.y; acc.z += v.z; acc.w += v.w;
    }
    float inv = (e > s) ? 1.f / (float)(e - s) : 0.f;
    acc.x *= inv; acc.y *= inv; acc.z *= inv; acc.w *= inv;
    *(float4*)(d_nmean + (size_t)warp * DD + lane * 4) = acc;
}

// ---------------- fused GEMM + bias + LayerNorm + ReLU -----------------------
// out[m][0:128] = relu(LN( concat(A1[m],A2[m]) @ W + b ))
// 64 rows x 128 cols per block, 256 threads, 8x4 accumulators per thread.
// tx = tid&31 picks 4 cols -> one warp covers a full row's 128 cols, so
// LayerNorm is 5 warp shuffles. ty = tid>>5 picks an 8-row group.
template <int K1, int K2, int A1B, int A2B, int OB>
__global__ void __launch_bounds__(256) gemm_ln_relu_kernel(
    const float* __restrict__ A1ext, float* __restrict__ Oext,
    const float* __restrict__ W, const float* __restrict__ bias,
    const float* __restrict__ gamma, const float* __restrict__ beta) {
    const float* __restrict__ A1 = cbuf_ptr<A1B>(A1ext);
    const float* __restrict__ A2 = cbuf_ptr<A2B>(nullptr);
    float* __restrict__ out = buf_ptr<OB>(Oext);

    constexpr int K = K1 + K2;
    constexpr int CH = 16;
    __shared__ float As[CH][68];   // [k][m], stride 68 floats (272B, 16B-aligned)
    __shared__ float Ws[CH][128];  // [k][col]

    const int tid = threadIdx.x;
    const int tx = tid & 31;
    const int ty = tid >> 5;
    const int row0 = blockIdx.x * 64;

    float acc[8][4];
#pragma unroll
    for (int r = 0; r < 8; r++)
#pragma unroll
        for (int c = 0; c < 4; c++) acc[r][c] = 0.f;

    for (int k0 = 0; k0 < K; k0 += CH) {
        // W tile: CH*128 = 2048 elems, 8/thread, coalesced
#pragma unroll
        for (int i = 0; i < 8; i++) {
            int idx = tid + i * 256;
            int kk = idx >> 7, col = idx & 127;
            int kg = k0 + kk;
            Ws[kk][col] = (kg < K) ? W[(size_t)kg * 128 + col] : 0.f;
        }
        // A tile: 64 rows x CH = 1024 elems, 4/thread
#pragma unroll
        for (int i = 0; i < 4; i++) {
            int idx = tid + i * 256;
            int m = idx >> 4;
            int kk = idx & 15;
            int kg = k0 + kk;
            int gr = row0 + m;
            float v = 0.f;
            if (gr < NN && kg < K) {
                if (kg < K1) v = A1[(size_t)gr * K1 + kg];
                else         v = A2[(size_t)gr * (K2 ? K2 : 1) + (kg - K1)];
            }
            As[kk][m] = v;
        }
        __syncthreads();
#pragma unroll
        for (int kk = 0; kk < CH; kk++) {
            float4 wv = *(const float4*)&Ws[kk][tx * 4];
            float4 a0 = *(const float4*)&As[kk][ty * 8];
            float4 a1 = *(const float4*)&As[kk][ty * 8 + 4];
            float av[8] = {a0.x, a0.y, a0.z, a0.w, a1.x, a1.y, a1.z, a1.w};
#pragma unroll
            for (int r = 0; r < 8; r++) {
                acc[r][0] += av[r] * wv.x;
                acc[r][1] += av[r] * wv.y;
                acc[r][2] += av[r] * wv.z;
                acc[r][3] += av[r] * wv.w;
            }
        }
        __syncthreads();
    }

    // epilogue: bias + LN + ReLU (warp-per-row shuffles)
    float4 bv = *(const float4*)&bias[tx * 4];
    float4 gv = *(const float4*)&gamma[tx * 4];
    float4 tv = *(const float4*)&beta[tx * 4];
#pragma unroll
    for (int r = 0; r < 8; r++) {
        int gr = row0 + ty * 8 + r;
        float x0 = acc[r][0] + bv.x;
        float x1 = acc[r][1] + bv.y;
        float x2 = acc[r][2] + bv.z;
        float x3 = acc[r][3] + bv.w;
        float s = x0 + x1 + x2 + x3;
        float q = x0 * x0 + x1 * x1 + x2 * x2 + x3 * x3;
#pragma unroll
        for (int off = 16; off > 0; off >>= 1) {
            s += __shfl_xor_sync(0xFFFFFFFFu, s, off);
            q += __shfl_xor_sync(0xFFFFFFFFu, q, off);
        }
        float mean = s * (1.f / 128.f);
        float var = q * (1.f / 128.f) - mean * mean;
        float rstd = rsqrtf(var + 1e-5f);
        float4 o;
        o.x = fmaxf((x0 - mean) * rstd * gv.x + tv.x, 0.f);
        o.y = fmaxf((x1 - mean) * rstd * gv.y + tv.y, 0.f);
        o.z = fmaxf((x2 - mean) * rstd * gv.z + tv.z, 0.f);
        o.w = fmaxf((x3 - mean) * rstd * gv.w + tv.w, 0.f);
        if (gr < NN) *(float4*)(out + (size_t)gr * 128 + tx * 4) = o;
    }
}

// ---------------- pooling accumulate (batch is sorted) -----------------------
__global__ void __launch_bounds__(128) pool_kernel(
    const float* __restrict__ ne, const int* __restrict__ batch) {
    __shared__ int sg[128];
    int col = threadIdx.x;
    int nb = blockIdx.x * 128;
    int rows = min(128, NN - nb);
    if (col < rows) sg[col] = batch[nb + col];
    __syncthreads();

    int cur = sg[0];
    float s = 0.f, mx = 0.f;
    for (int r = 0; r < rows; r++) {
        int g = sg[r];
        if (g != cur) {
            atomicAdd(&d_gsum[cur * DD + col], s);
            atomicMax(&d_gmax[cur * DD + col], __float_as_uint(mx));
            s = 0.f; mx = 0.f; cur = g;
        }
        float v = ne[(size_t)(nb + r) * DD + col];
        s += v;
        mx = fmaxf(mx, v);
    }
    atomicAdd(&d_gsum[cur * DD + col], s);
    atomicMax(&d_gmax[cur * DD + col], __float_as_uint(mx));
}

// ---------------- finalize graph embedding -----------------------------------
__global__ void finalize_kernel(float* __restrict__ gout) {
    int g = blockIdx.x;
    int col = threadIdx.x;
    float cnt = fmaxf((float)d_gcnt[g], 1.f);
    gout[g * 2 * DD + col] = d_gsum[g * DD + col] / cnt;
    gout[g * 2 * DD + DD + col] = __uint_as_float(d_gmax[g * DD + col]);
}

// ---------------- launch ------------------------------------------------------
extern "C" void kernel_launch(void* const* d_in, const int* in_sizes, int n_in,
                              void* d_out, int out_size) {
    const float* x     = (const float*)d_in[0];
    const int*   ei    = (const int*)d_in[1];     // int32 (JAX x64 disabled)
    const int*   batch = (const int*)d_in[2];     // int32
    const float* W_emb = (const float*)d_in[3];
    const float* b_emb = (const float*)d_in[4];
    const float* g0  = (const float*)d_in[5];
    const float* bt0 = (const float*)d_in[6];
    const float* Wc1 = (const float*)d_in[7];
    const float* bc1 = (const float*)d_in[8];
    const float* g1  = (const float*)d_in[9];
    const float* bt1 = (const float*)d_in[10];
    const float* Wc2 = (const float*)d_in[11];
    const float* bc2 = (const float*)d_in[12];
    const float* g2  = (const float*)d_in[13];
    const float* bt2 = (const float*)d_in[14];
    const float* Wc3 = (const float*)d_in[15];
    const float* bc3 = (const float*)d_in[16];
    const float* g3  = (const float*)d_in[17];
    const float* bt3 = (const float*)d_in[18];

    float* node_out  = (float*)d_out;                       // N*D
    float* graph_out = (float*)d_out + (size_t)NN * DD;     // G*2D

    // init + CSR build (reused by all 3 layers)
    init_kernel<<<(NN + 255) / 256, 256>>>();
    count_deg_kernel<<<(EE + 255) / 256, 256>>>(ei);
    gcnt_kernel<<<(NN + 255) / 256, 256>>>(batch);
    scan_kernel<<<1, 1024>>>();
    fill_csr_kernel<<<(EE + 255) / 256, 256>>>(ei);

    const int gemm_blocks = (NN + 63) / 64;
    const int agg_blocks  = (NN * 32 + 255) / 256;

    // node embedder: Linear(9->128) + LN + ReLU -> h0
    gemm_ln_relu_kernel<IN_F, 0, B_EXT, B_NM, B_H0><<<gemm_blocks, 256>>>(
        x, nullptr, W_emb, b_emb, g0, bt0);

    // SAGE layer 1: h0 -> h1
    aggregate_kernel<B_H0><<<agg_blocks, 256>>>();
    gemm_ln_relu_kernel<DD, DD, B_H0, B_NM, B_H1><<<gemm_blocks, 256>>>(
        nullptr, nullptr, Wc1, bc1, g1, bt1);

    // SAGE layer 2: h1 -> h0
    aggregate_kernel<B_H1><<<agg_blocks, 256>>>();
    gemm_ln_relu_kernel<DD, DD, B_H1, B_NM, B_H0><<<gemm_blocks, 256>>>(
        nullptr, nullptr, Wc2, bc2, g2, bt2);

    // SAGE layer 3: h0 -> node_out (d_out)
    aggregate_kernel<B_H0><<<agg_blocks, 256>>>();
    gemm_ln_relu_kernel<DD, DD, B_H0, B_NM, B_EXT><<<gemm_blocks, 256>>>(
        nullptr, node_out, Wc3, bc3, g3, bt3);

    // pooling
    pool_kernel<<<(NN + 127) / 128, 128>>>(node_out, batch);
    finalize_kernel<<<GG, DD>>>(graph_out);
}

// round 4
// speedup vs baseline: 1.1353x; 1.1353x over previous
#include <cuda_runtime.h>
#include <cuda_bf16.h>
#include <cstdint>

#define NN 50000
#define EE 1600000
#define DD 128
#define GG 64
#define IN_F 9
#define SCAN_G ((NN + 1023) / 1024)   // 49

// ---------------- scratch: __device__ globals, referenced directly ----------
__device__ float          d_h0[NN * DD];
__device__ float          d_h1[NN * DD];
__device__ float          d_nmean[NN * DD];
__device__ __nv_bfloat162 d_h0b[NN * DD / 2];   // bf16 copy of h0 (gather path)
__device__ __nv_bfloat162 d_h1b[NN * DD / 2];   // bf16 copy of h1
__device__ int            d_deg[NN];
__device__ int            d_cursor[NN];
__device__ int            d_rowstart[NN + 1];
__device__ int            d_csr[EE];
__device__ int            d_part[SCAN_G];
__device__ float          d_gsum[GG * DD];
__device__ unsigned       d_gmax[GG * DD];
__device__ int            d_gcnt[GG];

// buffer selectors (compile-time)
#define B_H0  0
#define B_H1  1
#define B_NM  2
#define B_EXT 3

template <int B>
__device__ __forceinline__ float* buf_ptr(float* ext) {
    if (B == B_H0) return d_h0;
    if (B == B_H1) return d_h1;
    if (B == B_NM) return d_nmean;
    return ext;
}
template <int B>
__device__ __forceinline__ const float* cbuf_ptr(const float* ext) {
    if (B == B_H0) return d_h0;
    if (B == B_H1) return d_h1;
    if (B == B_NM) return d_nmean;
    return ext;
}

// ---------------- init: zero counters/accumulators ---------------------------
__global__ void init_kernel() {
    int i = blockIdx.x * blockDim.x + threadIdx.x;
    if (i < NN) { d_deg[i] = 0; d_cursor[i] = 0; }
    if (i < GG) d_gcnt[i] = 0;
    if (i < GG * DD) { d_gsum[i] = 0.f; d_gmax[i] = 0u; }
}

// ---------------- degree count (edge_index is int32) -------------------------
__global__ void count_deg_kernel(const int* __restrict__ ei) {
    int e = blockIdx.x * blockDim.x + threadIdx.x;
    if (e < EE) atomicAdd(&d_deg[ei[EE + e]], 1);
}

// ---------------- graph node counts ------------------------------------------
__global__ void gcnt_kernel(const int* __restrict__ batch) {
    int n = blockIdx.x * blockDim.x + threadIdx.x;
    if (n < NN) atomicAdd(&d_gcnt[batch[n]], 1);
}

// ---------------- scan phase 1: per-block partial sums -----------------------
__global__ void scan_part_kernel() {
    __shared__ int sm[1024];
    int t = threadIdx.x;
    int i = blockIdx.x * 1024 + t;
    sm[t] = (i < NN) ? d_deg[i] : 0;
    __syncthreads();
    for (int off = 512; off > 0; off >>= 1) {
        if (t < off) sm[t] += sm[t + off];
        __syncthreads();
    }
    if (t == 0) d_part[blockIdx.x] = sm[0];
}

// ---------------- scan phase 2: exclusive-scan the 49 partials ---------------
__global__ void scan_mid_kernel() {
    if (threadIdx.x == 0) {
        int run = 0;
        for (int i = 0; i < SCAN_G; i++) {
            int v = d_part[i];
            d_part[i] = run;
            run += v;
        }
        d_rowstart[NN] = run;
    }
}

// ---------------- scan phase 3: block-local scan + offset --------------------
__global__ void scan_final_kernel() {
    __shared__ int sm[1024];
    int t = threadIdx.x;
    int i = blockIdx.x * 1024 + t;
    int v = (i < NN) ? d_deg[i] : 0;
    sm[t] = v;
    __syncthreads();
    for (int off = 1; off < 1024; off <<= 1) {
        int tmp = (t >= off) ? sm[t - off] : 0;
        __syncthreads();
        sm[t] += tmp;
        __syncthreads();
    }
    if (i < NN) d_rowstart[i] = d_part[blockIdx.x] + sm[t] - v;
}

// ---------------- CSR fill ---------------------------------------------------
__global__ void fill_csr_kernel(const int* __restrict__ ei) {
    int e = blockIdx.x * blockDim.x + threadIdx.x;
    if (e < EE) {
        int src = ei[e];
        int dst = ei[EE + e];
        int pos = d_rowstart[dst] + atomicAdd(&d_cursor[dst], 1);
        d_csr[pos] = src;
    }
}

// ---------------- neighbor mean aggregation (1 warp per dst node) -----------
// Reads the bf16 copy of h (half the L2 traffic), accumulates fp32.
template <int SB>
__global__ void __launch_bounds__(256) aggregate_kernel() {
    const __nv_bfloat162* __restrict__ hb = (SB == 0) ? d_h0b : d_h1b;
    int warp = (blockIdx.x * blockDim.x + threadIdx.x) >> 5;
    int lane = threadIdx.x & 31;
    if (warp >= NN) return;
    int s = d_rowstart[warp];
    int e = d_rowstart[warp + 1];
    float4 acc = make_float4(0.f, 0.f, 0.f, 0.f);
#pragma unroll 4
    for (int i = s; i < e; i++) {
        int src = d_csr[i];
        uint2 u = *reinterpret_cast<const uint2*>(hb + (size_t)src * 64 + lane * 2);
        __nv_bfloat162 b0 = *reinterpret_cast<const __nv_bfloat162*>(&u.x);
        __nv_bfloat162 b1 = *reinterpret_cast<const __nv_bfloat162*>(&u.y);
        float2 f0 = __bfloat1622float2(b0);
        float2 f1 = __bfloat1622float2(b1);
        acc.x += f0.x; acc.y += f0.y; acc.z += f1.x; acc.w += f1.y;
    }
    float inv = (e > s) ? 1.f / (float)(e - s) : 0.f;
    acc.x *= inv; acc.y *= inv; acc.z *= inv; acc.w *= inv;
    *(float4*)(d_nmean + (size_t)warp * DD + lane * 4) = acc;
}

// ---------------- fused GEMM + bias + LayerNorm + ReLU -----------------------
// out[m][0:128] = relu(LN( concat(A1[m],A2[m]) @ W + b ))
// 64 rows x 128 cols per block, 256 threads, 8x4 accumulators per thread.
// OBB: 0 = no bf16 copy, 1 = also write d_h0b, 2 = also write d_h1b.
template <int K1, int K2, int A1B, int A2B, int OB, int OBB>
__global__ void __launch_bounds__(256) gemm_ln_relu_kernel(
    const float* __restrict__ A1ext, float* __restrict__ Oext,
    const float* __restrict__ W, const float* __restrict__ bias,
    const float* __restrict__ gamma, const float* __restrict__ beta) {
    const float* __restrict__ A1 = cbuf_ptr<A1B>(A1ext);
    const float* __restrict__ A2 = cbuf_ptr<A2B>(nullptr);
    float* __restrict__ out = buf_ptr<OB>(Oext);

    constexpr int K = K1 + K2;
    constexpr int CH = 16;
    __shared__ float As[CH][68];
    __shared__ float Ws[CH][128];

    const int tid = threadIdx.x;
    const int tx = tid & 31;
    const int ty = tid >> 5;
    const int row0 = blockIdx.x * 64;

    float acc[8][4];
#pragma unroll
    for (int r = 0; r < 8; r++)
#pragma unroll
        for (int c = 0; c < 4; c++) acc[r][c] = 0.f;

    for (int k0 = 0; k0 < K; k0 += CH) {
#pragma unroll
        for (int i = 0; i < 8; i++) {
            int idx = tid + i * 256;
            int kk = idx >> 7, col = idx & 127;
            int kg = k0 + kk;
            Ws[kk][col] = (kg < K) ? W[(size_t)kg * 128 + col] : 0.f;
        }
#pragma unroll
        for (int i = 0; i < 4; i++) {
            int idx = tid + i * 256;
            int m = idx >> 4;
            int kk = idx & 15;
            int kg = k0 + kk;
            int gr = row0 + m;
            float v = 0.f;
            if (gr < NN && kg < K) {
                if (kg < K1) v = A1[(size_t)gr * K1 + kg];
                else         v = A2[(size_t)gr * (K2 ? K2 : 1) + (kg - K1)];
            }
            As[kk][m] = v;
        }
        __syncthreads();
#pragma unroll
        for (int kk = 0; kk < CH; kk++) {
            float4 wv = *(const float4*)&Ws[kk][tx * 4];
            float4 a0 = *(const float4*)&As[kk][ty * 8];
            float4 a1 = *(const float4*)&As[kk][ty * 8 + 4];
            float av[8] = {a0.x, a0.y, a0.z, a0.w, a1.x, a1.y, a1.z, a1.w};
#pragma unroll
            for (int r = 0; r < 8; r++) {
                acc[r][0] += av[r] * wv.x;
                acc[r][1] += av[r] * wv.y;
                acc[r][2] += av[r] * wv.z;
                acc[r][3] += av[r] * wv.w;
            }
        }
        __syncthreads();
    }

    // epilogue: bias + LN + ReLU (warp-per-row shuffles)
    float4 bv = *(const float4*)&bias[tx * 4];
    float4 gv = *(const float4*)&gamma[tx * 4];
    float4 tv = *(const float4*)&beta[tx * 4];
#pragma unroll
    for (int r = 0; r < 8; r++) {
        int gr = row0 + ty * 8 + r;
        float x0 = acc[r][0] + bv.x;
        float x1 = acc[r][1] + bv.y;
        float x2 = acc[r][2] + bv.z;
        float x3 = acc[r][3] + bv.w;
        float s = x0 + x1 + x2 + x3;
        float q = x0 * x0 + x1 * x1 + x2 * x2 + x3 * x3;
#pragma unroll
        for (int off = 16; off > 0; off >>= 1) {
            s += __shfl_xor_sync(0xFFFFFFFFu, s, off);
            q += __shfl_xor_sync(0xFFFFFFFFu, q, off);
        }
        float mean = s * (1.f / 128.f);
        float var = q * (1.f / 128.f) - mean * mean;
        float rstd = rsqrtf(var + 1e-5f);
        float4 o;
        o.x = fmaxf((x0 - mean) * rstd * gv.x + tv.x, 0.f);
        o.y = fmaxf((x1 - mean) * rstd * gv.y + tv.y, 0.f);
        o.z = fmaxf((x2 - mean) * rstd * gv.z + tv.z, 0.f);
        o.w = fmaxf((x3 - mean) * rstd * gv.w + tv.w, 0.f);
        if (gr < NN) {
            *(float4*)(out + (size_t)gr * 128 + tx * 4) = o;
            if (OBB != 0) {
                __nv_bfloat162* hb = (OBB == 1) ? d_h0b : d_h1b;
                __nv_bfloat162 b0 = __float22bfloat162_rn(make_float2(o.x, o.y));
                __nv_bfloat162 b1 = __float22bfloat162_rn(make_float2(o.z, o.w));
                uint2 u;
                u.x = *reinterpret_cast<unsigned*>(&b0);
                u.y = *reinterpret_cast<unsigned*>(&b1);
                *reinterpret_cast<uint2*>(hb + (size_t)gr * 64 + tx * 2) = u;
            }
        }
    }
}

// ---------------- pooling accumulate (batch is sorted) -----------------------
__global__ void __launch_bounds__(128) pool_kernel(
    const float* __restrict__ ne, const int* __restrict__ batch) {
    __shared__ int sg[128];
    int col = threadIdx.x;
    int nb = blockIdx.x * 128;
    int rows = min(128, NN - nb);
    if (col < rows) sg[col] = batch[nb + col];
    __syncthreads();

    int cur = sg[0];
    float s = 0.f, mx = 0.f;
    for (int r = 0; r < rows; r++) {
        int g = sg[r];
        if (g != cur) {
            atomicAdd(&d_gsum[cur * DD + col], s);
            atomicMax(&d_gmax[cur * DD + col], __float_as_uint(mx));
            s = 0.f; mx = 0.f; cur = g;
        }
        float v = ne[(size_t)(nb + r) * DD + col];
        s += v;
        mx = fmaxf(mx, v);
    }
    atomicAdd(&d_gsum[cur * DD + col], s);
    atomicMax(&d_gmax[cur * DD + col], __float_as_uint(mx));
}

// ---------------- finalize graph embedding -----------------------------------
__global__ void finalize_kernel(float* __restrict__ gout) {
    int g = blockIdx.x;
    int col = threadIdx.x;
    float cnt = fmaxf((float)d_gcnt[g], 1.f);
    gout[g * 2 * DD + col] = d_gsum[g * DD + col] / cnt;
    gout[g * 2 * DD + DD + col] = __uint_as_float(d_gmax[g * DD + col]);
}

// ---------------- launch ------------------------------------------------------
extern "C" void kernel_launch(void* const* d_in, const int* in_sizes, int n_in,
                              void* d_out, int out_size) {
    const float* x     = (const float*)d_in[0];
    const int*   ei    = (const int*)d_in[1];     // int32
    const int*   batch = (const int*)d_in[2];     // int32
    const float* W_emb = (const float*)d_in[3];
    const float* b_emb = (const float*)d_in[4];
    const float* g0  = (const float*)d_in[5];
    const float* bt0 = (const float*)d_in[6];
    const float* Wc1 = (const float*)d_in[7];
    const float* bc1 = (const float*)d_in[8];
    const float* g1  = (const float*)d_in[9];
    const float* bt1 = (const float*)d_in[10];
    const float* Wc2 = (const float*)d_in[11];
    const float* bc2 = (const float*)d_in[12];
    const float* g2  = (const float*)d_in[13];
    const float* bt2 = (const float*)d_in[14];
    const float* Wc3 = (const float*)d_in[15];
    const float* bc3 = (const float*)d_in[16];
    const float* g3  = (const float*)d_in[17];
    const float* bt3 = (const float*)d_in[18];

    float* node_out  = (float*)d_out;                       // N*D
    float* graph_out = (float*)d_out + (size_t)NN * DD;     // G*2D

    // init + CSR build (reused by all 3 layers)
    init_kernel<<<(NN + 255) / 256, 256>>>();
    count_deg_kernel<<<(EE + 255) / 256, 256>>>(ei);
    gcnt_kernel<<<(NN + 255) / 256, 256>>>(batch);
    scan_part_kernel<<<SCAN_G, 1024>>>();
    scan_mid_kernel<<<1, 32>>>();
    scan_final_kernel<<<SCAN_G, 1024>>>();
    fill_csr_kernel<<<(EE + 255) / 256, 256>>>(ei);

    const int gemm_blocks = (NN + 63) / 64;
    const int agg_blocks  = (NN * 32 + 255) / 256;

    // node embedder: Linear(9->128) + LN + ReLU -> h0 (+ bf16 copy)
    gemm_ln_relu_kernel<IN_F, 0, B_EXT, B_NM, B_H0, 1><<<gemm_blocks, 256>>>(
        x, nullptr, W_emb, b_emb, g0, bt0);

    // SAGE layer 1: h0 -> h1
    aggregate_kernel<0><<<agg_blocks, 256>>>();
    gemm_ln_relu_kernel<DD, DD, B_H0, B_NM, B_H1, 2><<<gemm_blocks, 256>>>(
        nullptr, nullptr, Wc1, bc1, g1, bt1);

    // SAGE layer 2: h1 -> h0
    aggregate_kernel<1><<<agg_blocks, 256>>>();
    gemm_ln_relu_kernel<DD, DD, B_H1, B_NM, B_H0, 1><<<gemm_blocks, 256>>>(
        nullptr, nullptr, Wc2, bc2, g2, bt2);

    // SAGE layer 3: h0 -> node_out (d_out), no bf16 copy needed
    aggregate_kernel<0><<<agg_blocks, 256>>>();
    gemm_ln_relu_kernel<DD, DD, B_H0, B_NM, B_EXT, 0><<<gemm_blocks, 256>>>(
        nullptr, node_out, Wc3, bc3, g3, bt3);

    // pooling
    pool_kernel<<<(NN + 127) / 128, 128>>>(node_out, batch);
    finalize_kernel<<<GG, DD>>>(graph_out);
}

// round 5
// speedup vs baseline: 1.1436x; 1.0073x over previous
#include <cuda_runtime.h>
#include <cuda_bf16.h>
#include <cstdint>

#define NN 50000
#define EE 1600000
#define DD 128
#define GG 64
#define IN_F 9
#define SCAN_G ((NN + 1023) / 1024)   // 49

typedef unsigned long long ull;

// ---------------- f32x2 packed-math helpers (Blackwell, PTX-only) ------------
__device__ __forceinline__ ull pack2(float x, float y) {
    ull r; asm("mov.b64 %0, {%1, %2};" : "=l"(r) : "f"(x), "f"(y)); return r;
}
__device__ __forceinline__ void unpack2(ull v, float& x, float& y) {
    asm("mov.b64 {%0, %1}, %2;" : "=f"(x), "=f"(y) : "l"(v));
}
__device__ __forceinline__ void ffma2(ull& d, ull a, ull b) {
    asm("fma.rn.f32x2 %0, %1, %2, %3;" : "=l"(d) : "l"(a), "l"(b), "l"(d));
}

// ---------------- scratch: __device__ globals, referenced directly ----------
__device__ float          d_h0[NN * DD];
__device__ float          d_h1[NN * DD];
__device__ float          d_nmean[NN * DD];
__device__ __nv_bfloat162 d_h0b[NN * DD / 2];
__device__ __nv_bfloat162 d_h1b[NN * DD / 2];
__device__ int            d_deg[NN];
__device__ int            d_cursor[NN];
__device__ int            d_rowstart[NN + 1];
__device__ int            d_csr[EE];
__device__ int            d_part[SCAN_G];
__device__ float          d_gsum[GG * DD];
__device__ unsigned       d_gmax[GG * DD];
__device__ int            d_gcnt[GG];

// buffer selectors (compile-time)
#define B_H0  0
#define B_H1  1
#define B_NM  2
#define B_EXT 3

template <int B>
__device__ __forceinline__ float* buf_ptr(float* ext) {
    if (B == B_H0) return d_h0;
    if (B == B_H1) return d_h1;
    if (B == B_NM) return d_nmean;
    return ext;
}
template <int B>
__device__ __forceinline__ const float* cbuf_ptr(const float* ext) {
    if (B == B_H0) return d_h0;
    if (B == B_H1) return d_h1;
    if (B == B_NM) return d_nmean;
    return ext;
}

// ---------------- init ---------------------------------------------------
__global__ void init_kernel() {
    int i = blockIdx.x * blockDim.x + threadIdx.x;
    if (i < NN) { d_deg[i] = 0; d_cursor[i] = 0; }
    if (i < GG) d_gcnt[i] = 0;
    if (i < GG * DD) { d_gsum[i] = 0.f; d_gmax[i] = 0u; }
}

// ---------------- degree count -----------------------------------------------
__global__ void count_deg_kernel(const int* __restrict__ ei) {
    int e = blockIdx.x * blockDim.x + threadIdx.x;
    if (e < EE) atomicAdd(&d_deg[ei[EE + e]], 1);
}

// ---------------- graph node counts ------------------------------------------
__global__ void gcnt_kernel(const int* __restrict__ batch) {
    int n = blockIdx.x * blockDim.x + threadIdx.x;
    if (n < NN) atomicAdd(&d_gcnt[batch[n]], 1);
}

// ---------------- scan phase 1: per-block partial sums -----------------------
__global__ void scan_part_kernel() {
    __shared__ int sm[1024];
    int t = threadIdx.x;
    int i = blockIdx.x * 1024 + t;
    sm[t] = (i < NN) ? d_deg[i] : 0;
    __syncthreads();
    for (int off = 512; off > 0; off >>= 1) {
        if (t < off) sm[t] += sm[t + off];
        __syncthreads();
    }
    if (t == 0) d_part[blockIdx.x] = sm[0];
}

// ---------------- scan phase 2 ----------------------------------------------
__global__ void scan_mid_kernel() {
    if (threadIdx.x == 0) {
        int run = 0;
        for (int i = 0; i < SCAN_G; i++) {
            int v = d_part[i];
            d_part[i] = run;
            run += v;
        }
        d_rowstart[NN] = run;
    }
}

// ---------------- scan phase 3 ----------------------------------------------
__global__ void scan_final_kernel() {
    __shared__ int sm[1024];
    int t = threadIdx.x;
    int i = blockIdx.x * 1024 + t;
    int v = (i < NN) ? d_deg[i] : 0;
    sm[t] = v;
    __syncthreads();
    for (int off = 1; off < 1024; off <<= 1) {
        int tmp = (t >= off) ? sm[t - off] : 0;
        __syncthreads();
        sm[t] += tmp;
        __syncthreads();
    }
    if (i < NN) d_rowstart[i] = d_part[blockIdx.x] + sm[t] - v;
}

// ---------------- CSR fill ---------------------------------------------------
__global__ void fill_csr_kernel(const int* __restrict__ ei) {
    int e = blockIdx.x * blockDim.x + threadIdx.x;
    if (e < EE) {
        int src = ei[e];
        int dst = ei[EE + e];
        int pos = d_rowstart[dst] + atomicAdd(&d_cursor[dst], 1);
        d_csr[pos] = src;
    }
}

// ---------------- neighbor mean aggregation (1 warp per dst node) -----------
template <int SB>
__global__ void __launch_bounds__(256) aggregate_kernel() {
    const __nv_bfloat162* __restrict__ hb = (SB == 0) ? d_h0b : d_h1b;
    int warp = (blockIdx.x * blockDim.x + threadIdx.x) >> 5;
    int lane = threadIdx.x & 31;
    if (warp >= NN) return;
    int s = d_rowstart[warp];
    int e = d_rowstart[warp + 1];
    float4 acc = make_float4(0.f, 0.f, 0.f, 0.f);
#pragma unroll 4
    for (int i = s; i < e; i++) {
        int src = d_csr[i];
        uint2 u = *reinterpret_cast<const uint2*>(hb + (size_t)src * 64 + lane * 2);
        __nv_bfloat162 b0 = *reinterpret_cast<const __nv_bfloat162*>(&u.x);
        __nv_bfloat162 b1 = *reinterpret_cast<const __nv_bfloat162*>(&u.y);
        float2 f0 = __bfloat1622float2(b0);
        float2 f1 = __bfloat1622float2(b1);
        acc.x += f0.x; acc.y += f0.y; acc.z += f1.x; acc.w += f1.y;
    }
    float inv = (e > s) ? 1.f / (float)(e - s) : 0.f;
    acc.x *= inv; acc.y *= inv; acc.z *= inv; acc.w *= inv;
    *(float4*)(d_nmean + (size_t)warp * DD + lane * 4) = acc;
}

// ---------------- fused GEMM + bias + LayerNorm + ReLU (f32x2 core) ----------
// out[m][0:128] = relu(LN( concat(A1[m],A2[m]) @ W + b ))
// 64 rows x 128 cols per block, 256 threads, 8 rows x 4 cols per thread,
// accumulators held as packed f32x2 pairs, inner product via fma.rn.f32x2.
template <int K1, int K2, int A1B, int A2B, int OB, int OBB>
__global__ void __launch_bounds__(256) gemm_ln_relu_kernel(
    const float* __restrict__ A1ext, float* __restrict__ Oext,
    const float* __restrict__ W, const float* __restrict__ bias,
    const float* __restrict__ gamma, const float* __restrict__ beta) {
    const float* __restrict__ A1 = cbuf_ptr<A1B>(A1ext);
    const float* __restrict__ A2 = cbuf_ptr<A2B>(nullptr);
    float* __restrict__ out = buf_ptr<OB>(Oext);

    constexpr int K = K1 + K2;
    constexpr int CH = 32;
    __shared__ float As[CH][68];    // [k][m]
    __shared__ float Ws[CH][128];   // [k][col]

    const int tid = threadIdx.x;
    const int tx = tid & 31;
    const int ty = tid >> 5;
    const int row0 = blockIdx.x * 64;

    ull acc2[8][2];
#pragma unroll
    for (int r = 0; r < 8; r++) { acc2[r][0] = 0ull; acc2[r][1] = 0ull; }

    for (int k0 = 0; k0 < K; k0 += CH) {
        // W tile: CH*128 = 4096 elems, 16/thread, coalesced
#pragma unroll
        for (int i = 0; i < 16; i++) {
            int idx = tid + i * 256;
            int kk = idx >> 7, col = idx & 127;
            int kg = k0 + kk;
            Ws[kk][col] = (kg < K) ? W[(size_t)kg * 128 + col] : 0.f;
        }
        // A tile: 64 rows x CH = 2048 elems, 8/thread
#pragma unroll
        for (int i = 0; i < 8; i++) {
            int idx = tid + i * 256;
            int m = idx >> 5;
            int kk = idx & 31;
            int kg = k0 + kk;
            int gr = row0 + m;
            float v = 0.f;
            if (gr < NN && kg < K) {
                if (kg < K1) v = A1[(size_t)gr * K1 + kg];
                else         v = A2[(size_t)gr * (K2 ? K2 : 1) + (kg - K1)];
            }
            As[kk][m] = v;
        }
        __syncthreads();
#pragma unroll 8
        for (int kk = 0; kk < CH; kk++) {
            ulonglong2 wp = *(const ulonglong2*)&Ws[kk][tx * 4];
            float4 a0 = *(const float4*)&As[kk][ty * 8];
            float4 a1 = *(const float4*)&As[kk][ty * 8 + 4];
            float av[8] = {a0.x, a0.y, a0.z, a0.w, a1.x, a1.y, a1.z, a1.w};
#pragma unroll
            for (int r = 0; r < 8; r++) {
                ull ap = pack2(av[r], av[r]);
                ffma2(acc2[r][0], ap, wp.x);
                ffma2(acc2[r][1], ap, wp.y);
            }
        }
        __syncthreads();
    }

    // epilogue: bias + LN + ReLU (warp-per-row shuffles)
    float4 bv = *(const float4*)&bias[tx * 4];
    float4 gv = *(const float4*)&gamma[tx * 4];
    float4 tv = *(const float4*)&beta[tx * 4];
#pragma unroll
    for (int r = 0; r < 8; r++) {
        int gr = row0 + ty * 8 + r;
        float x0, x1, x2, x3;
        unpack2(acc2[r][0], x0, x1);
        unpack2(acc2[r][1], x2, x3);
        x0 += bv.x; x1 += bv.y; x2 += bv.z; x3 += bv.w;
        float s = x0 + x1 + x2 + x3;
        float q = x0 * x0 + x1 * x1 + x2 * x2 + x3 * x3;
#pragma unroll
        for (int off = 16; off > 0; off >>= 1) {
            s += __shfl_xor_sync(0xFFFFFFFFu, s, off);
            q += __shfl_xor_sync(0xFFFFFFFFu, q, off);
        }
        float mean = s * (1.f / 128.f);
        float var = q * (1.f / 128.f) - mean * mean;
        float rstd = rsqrtf(var + 1e-5f);
        float4 o;
        o.x = fmaxf((x0 - mean) * rstd * gv.x + tv.x, 0.f);
        o.y = fmaxf((x1 - mean) * rstd * gv.y + tv.y, 0.f);
        o.z = fmaxf((x2 - mean) * rstd * gv.z + tv.z, 0.f);
        o.w = fmaxf((x3 - mean) * rstd * gv.w + tv.w, 0.f);
        if (gr < NN) {
            *(float4*)(out + (size_t)gr * 128 + tx * 4) = o;
            if (OBB != 0) {
                __nv_bfloat162* hb = (OBB == 1) ? d_h0b : d_h1b;
                __nv_bfloat162 b0 = __float22bfloat162_rn(make_float2(o.x, o.y));
                __nv_bfloat162 b1 = __float22bfloat162_rn(make_float2(o.z, o.w));
                uint2 u;
                u.x = *reinterpret_cast<unsigned*>(&b0);
                u.y = *reinterpret_cast<unsigned*>(&b1);
                *reinterpret_cast<uint2*>(hb + (size_t)gr * 64 + tx * 2) = u;
            }
        }
    }
}

// ---------------- pooling accumulate (batch is sorted) -----------------------
__global__ void __launch_bounds__(128) pool_kernel(
    const float* __restrict__ ne, const int* __restrict__ batch) {
    __shared__ int sg[128];
    int col = threadIdx.x;
    int nb = blockIdx.x * 128;
    int rows = min(128, NN - nb);
    if (col < rows) sg[col] = batch[nb + col];
    __syncthreads();

    int cur = sg[0];
    float s = 0.f, mx = 0.f;
    for (int r = 0; r < rows; r++) {
        int g = sg[r];
        if (g != cur) {
            atomicAdd(&d_gsum[cur * DD + col], s);
            atomicMax(&d_gmax[cur * DD + col], __float_as_uint(mx));
            s = 0.f; mx = 0.f; cur = g;
        }
        float v = ne[(size_t)(nb + r) * DD + col];
        s += v;
        mx = fmaxf(mx, v);
    }
    atomicAdd(&d_gsum[cur * DD + col], s);
    atomicMax(&d_gmax[cur * DD + col], __float_as_uint(mx));
}

// ---------------- finalize graph embedding -----------------------------------
__global__ void finalize_kernel(float* __restrict__ gout) {
    int g = blockIdx.x;
    int col = threadIdx.x;
    float cnt = fmaxf((float)d_gcnt[g], 1.f);
    gout[g * 2 * DD + col] = d_gsum[g * DD + col] / cnt;
    gout[g * 2 * DD + DD + col] = __uint_as_float(d_gmax[g * DD + col]);
}

// ---------------- launch ------------------------------------------------------
extern "C" void kernel_launch(void* const* d_in, const int* in_sizes, int n_in,
                              void* d_out, int out_size) {
    const float* x     = (const float*)d_in[0];
    const int*   ei    = (const int*)d_in[1];
    const int*   batch = (const int*)d_in[2];
    const float* W_emb = (const float*)d_in[3];
    const float* b_emb = (const float*)d_in[4];
    const float* g0  = (const float*)d_in[5];
    const float* bt0 = (const float*)d_in[6];
    const float* Wc1 = (const float*)d_in[7];
    const float* bc1 = (const float*)d_in[8];
    const float* g1  = (const float*)d_in[9];
    const float* bt1 = (const float*)d_in[10];
    const float* Wc2 = (const float*)d_in[11];
    const float* bc2 = (const float*)d_in[12];
    const float* g2  = (const float*)d_in[13];
    const float* bt2 = (const float*)d_in[14];
    const float* Wc3 = (const float*)d_in[15];
    const float* bc3 = (const float*)d_in[16];
    const float* g3  = (const float*)d_in[17];
    const float* bt3 = (const float*)d_in[18];

    float* node_out  = (float*)d_out;
    float* graph_out = (float*)d_out + (size_t)NN * DD;

    init_kernel<<<(NN + 255) / 256, 256>>>();
    count_deg_kernel<<<(EE + 255) / 256, 256>>>(ei);
    gcnt_kernel<<<(NN + 255) / 256, 256>>>(batch);
    scan_part_kernel<<<SCAN_G, 1024>>>();
    scan_mid_kernel<<<1, 32>>>();
    scan_final_kernel<<<SCAN_G, 1024>>>();
    fill_csr_kernel<<<(EE + 255) / 256, 256>>>(ei);

    const int gemm_blocks = (NN + 63) / 64;
    const int agg_blocks  = (NN * 32 + 255) / 256;

    // node embedder: Linear(9->128) + LN + ReLU -> h0 (+ bf16 copy)
    gemm_ln_relu_kernel<IN_F, 0, B_EXT, B_NM, B_H0, 1><<<gemm_blocks, 256>>>(
        x, nullptr, W_emb, b_emb, g0, bt0);

    // SAGE layer 1: h0 -> h1
    aggregate_kernel<0><<<agg_blocks, 256>>>();
    gemm_ln_relu_kernel<DD, DD, B_H0, B_NM, B_H1, 2><<<gemm_blocks, 256>>>(
        nullptr, nullptr, Wc1, bc1, g1, bt1);

    // SAGE layer 2: h1 -> h0
    aggregate_kernel<1><<<agg_blocks, 256>>>();
    gemm_ln_relu_kernel<DD, DD, B_H1, B_NM, B_H0, 1><<<gemm_blocks, 256>>>(
        nullptr, nullptr, Wc2, bc2, g2, bt2);

    // SAGE layer 3: h0 -> node_out
    aggregate_kernel<0><<<agg_blocks, 256>>>();
    gemm_ln_relu_kernel<DD, DD, B_H0, B_NM, B_EXT, 0><<<gemm_blocks, 256>>>(
        nullptr, node_out, Wc3, bc3, g3, bt3);

    // pooling
    pool_kernel<<<(NN + 127) / 128, 128>>>(node_out, batch);
    finalize_kernel<<<GG, DD>>>(graph_out);
}